// round 12
// baseline (speedup 1.0000x reference)
#include <cuda_runtime.h>

#define NBOX 4096
#define T 1024
#define PER 4                  // NBOX / T
#define NWARP 32
#define PROD (NWARP - 1)       // producer = HIGHEST wid (hi-wid-first arbiter)
#define BMAX 64
#define THRESH 0.05f
#define FULL 0xffffffffu

__device__ float4 g_sbox[NBOX];
__device__ int    g_orig[NBOX];

__device__ __forceinline__ int ld_acq(const int* p) {
    int v;
    asm volatile("ld.acquire.cta.b32 %0, [%1];" : "=r"(v) : "l"(p) : "memory");
    return v;
}
__device__ __forceinline__ void st_rel(int* p, int v) {
    asm volatile("st.release.cta.b32 [%0], %1;" :: "l"(p), "r"(v) : "memory");
}

__global__ __launch_bounds__(T, 1)
void softnms_kernel(const float4* __restrict__ boxes,
                    const float*  __restrict__ scores,
                    float* __restrict__ out, int out_size)
{
    __shared__ unsigned long long skv[NBOX];   // sort scratch
    __shared__ uint4    spoolA[NWARP];         // (k1, p1, k2, p2) exact keys
    __shared__ unsigned sm3[NWARP];            // per-warp 3rd-best value
    __shared__ float4   sbatch_box[BMAX];
    __shared__ uint2    sbatch_meta[BMAX];     // (sorted pos, exact score bits)
    __shared__ int      spub, sdone;           // sdone: B | fz<<8 | fp<<9

    const int t    = threadIdx.x;
    const int lane = t & 31;
    const int wid  = t >> 5;

    // ---- init: zero score outputs, stage u64 sort keys ----
#pragma unroll
    for (int k = 0; k < PER; k++) {
        const int gi = t * PER + k;
        if (gi < out_size) out[gi] = 0.0f;
        skv[gi] = ((unsigned long long)__float_as_uint(boxes[gi].x) << 32)
                  | (unsigned)gi;
    }
    __syncthreads();

    // ---- bitonic sort ascending by x1 ----
    for (int k = 2; k <= NBOX; k <<= 1) {
        for (int j = k >> 1; j > 0; j >>= 1) {
#pragma unroll
            for (int e = t; e < NBOX; e += T) {
                const int ixj = e ^ j;
                if (ixj > e) {
                    const unsigned long long a = skv[e], c = skv[ixj];
                    const bool up = ((e & k) == 0);
                    if (up ? (a > c) : (a < c)) { skv[e] = c; skv[ixj] = a; }
                }
            }
            __syncthreads();
        }
    }

    // ---- load my PER sorted boxes; publish sorted tables ----
    float x1[PER], y1[PER], x2[PER], y2[PER], area[PER], s[PER];
    int   orig[PER];
    unsigned procm = 0;
    float tx2hi = 0.0f;
#pragma unroll
    for (int k = 0; k < PER; k++) {
        const int pos = t * PER + k;
        const int o   = (int)(unsigned)(skv[pos] & 0xffffffffu);
        orig[k] = o;
        const float4 b = boxes[o];
        x1[k] = b.x; y1[k] = b.y; x2[k] = b.z; y2[k] = b.w;
        area[k] = (b.z - b.x) * (b.w - b.y);
        s[k]    = scores[o];
        g_sbox[pos] = b;
        g_orig[pos] = o;
        tx2hi = fmaxf(tx2hi, b.z);
    }
    const float tx1lo = x1[0];
    __syncthreads();

    bool dirty = true;
    int  step  = 0;
    int  fro_final = 0, fpos_final = 0;

    while (step < NBOX) {
        // ========= rebuild per-warp top-2 (+3rd value), EXACT argmax =======
        if (__ballot_sync(FULL, dirty)) {
            unsigned b1 = 0, b2 = 0, b3 = 0, p1 = 0, p2 = 0;
#pragma unroll
            for (int k = 0; k < PER; k++) {
                if (!((procm >> k) & 1u)) {
                    const unsigned ub = __float_as_uint(s[k]);   // scores > 0
                    const unsigned up = (unsigned)(t * PER + k);
                    if (ub > b1)      { b3 = b2; b2 = b1; p2 = p1; b1 = ub; p1 = up; }
                    else if (ub > b2) { b3 = b2; b2 = ub; p2 = up; }
                    else if (ub > b3) { b3 = ub; }
                }
            }
            const unsigned m1   = __reduce_max_sync(FULL, b1);
            const unsigned bal1 = __ballot_sync(FULL, b1 == m1);
            const int s1        = __ffs(bal1) - 1;
            const unsigned q1   = __shfl_sync(FULL, p1, s1);
            const unsigned v2   = (lane == s1) ? b2 : b1;
            const unsigned vp2  = (lane == s1) ? p2 : p1;
            const unsigned m2   = __reduce_max_sync(FULL, v2);
            const unsigned bal2 = __ballot_sync(FULL, v2 == m2);
            const int s2        = __ffs(bal2) - 1;
            const unsigned q2   = __shfl_sync(FULL, vp2, s2);
            unsigned v3 = b1;
            if (lane == s1) v3 = b2;
            if (lane == s2) v3 = (s2 == s1) ? b3 : b2;
            const unsigned m3 = __reduce_max_sync(FULL, v3);
            if (lane == 0) { spoolA[wid] = make_uint4(m1, q1, m2, q2); sm3[wid] = m3; }
            dirty = false;
        }
        if (t == 0) { spub = 0; sdone = -1; }
        __syncthreads();   // bar1: pools + flags visible

        if (wid == PROD) {
            // == producer: speculative batch scan (expf off critical path) ==
            const uint4 a = spoolA[lane];
            unsigned k1 = a.x, pp1 = a.y, k2 = a.z, pp2 = a.w;
            const unsigned M3 = __reduce_max_sync(FULL, sm3[lane]);
            const float4 f1 = g_sbox[pp1]; const float a1 = (f1.z - f1.x) * (f1.w - f1.y);
            const float4 f2 = g_sbox[pp2]; const float a2 = (f2.z - f2.x) * (f2.w - f2.y);

            int B = 0, fz = 0; unsigned fp = 0;

            // initial exact selection
            bool s1w      = (k1 >= k2);
            unsigned kmax = s1w ? k1 : k2;
            unsigned m    = __reduce_max_sync(FULL, kmax);
            unsigned bal  = __ballot_sync(FULL, kmax == m);
            int src       = __ffs(bal) - 1;

            while (true) {
                if (m < M3) break;                   // pool no longer covers order
                if (!(__uint_as_float(m) > THRESH)) {  // pool max == global max
                    fz = 1;
                    fp = __shfl_sync(FULL, s1w ? pp1 : pp2, src);
                    break;
                }
                // member coords from winner's registers
                const float mx1 = __shfl_sync(FULL, s1w ? f1.x : f2.x, src);
                const float my1 = __shfl_sync(FULL, s1w ? f1.y : f2.y, src);
                const float mx2 = __shfl_sync(FULL, s1w ? f1.z : f2.z, src);
                const float my2 = __shfl_sync(FULL, s1w ? f1.w : f2.w, src);
                const float mar = (mx2 - mx1) * (my2 - my1);
                const bool is_src = (lane == src);
                if (is_src) {
                    sbatch_box[B]  = make_float4(mx1, my1, mx2, my2);
                    sbatch_meta[B] = make_uint2(s1w ? pp1 : pp2, m);
                    st_rel(&spub, B + 1);
                }
                // consume winner slot (0 stays 0 through decays)
                k1 = (is_src &&  s1w) ? 0u : k1;
                k2 = (is_src && !s1w) ? 0u : k2;
                B++;
                if (B == BMAX) break;

                // ---- speculative next selection on PRE-decay keys ----
                const bool s1w_n      = (k1 >= k2);
                const unsigned kmax_n = s1w_n ? k1 : k2;
                const unsigned m_s    = __reduce_max_sync(FULL, kmax_n);
                const unsigned bal_s  = __ballot_sync(FULL, kmax_n == m_s);
                const int src_s       = __ffs(bal_s) - 1;

                // ---- fast overlap flags (cheap, parallel with REDUX) ----
                const float iw1 = fmaxf(fminf(mx2, f1.z) - fmaxf(mx1, f1.x), 0.0f);
                const float ih1 = fmaxf(fminf(my2, f1.w) - fmaxf(my1, f1.y), 0.0f);
                const float inter1 = iw1 * ih1;
                const float iw2 = fmaxf(fminf(mx2, f2.z) - fmaxf(mx1, f2.x), 0.0f);
                const float ih2 = fmaxf(fminf(my2, f2.w) - fmaxf(my1, f2.y), 0.0f);
                const float inter2 = iw2 * ih2;
                const bool ovmax = s1w_n ? (inter1 > 0.0f) : (inter2 > 0.0f);
                const unsigned ovm = __ballot_sync(FULL, ovmax);

                // ---- decay both slots (bit-exact; off-chain if spec valid) --
                {
                    const float iou = __fdividef(inter1, mar + a1 - inter1);
                    k1 = __float_as_uint(__uint_as_float(k1) * __expf(-2.0f * iou * iou));
                }
                {
                    const float iou = __fdividef(inter2, mar + a2 - inter2);
                    k2 = __float_as_uint(__uint_as_float(k2) * __expf(-2.0f * iou * iou));
                }

                if (!((ovm >> src_s) & 1u)) {
                    // speculation exact: winner's slot untouched by this decay
                    m = m_s; src = src_s; s1w = s1w_n;
                } else {
                    // mis-spec: redo selection on decayed keys
                    s1w  = (k1 >= k2);
                    kmax = s1w ? k1 : k2;
                    m    = __reduce_max_sync(FULL, kmax);
                    bal  = __ballot_sync(FULL, kmax == m);
                    src  = __ffs(bal) - 1;
                }
            }
            __syncwarp();                            // fence all lanes' stores
            if (lane == 0)
                st_rel(&sdone, B | (fz << 8) | ((int)fp << 9));
            // ---- producer applies the batch to its own slab ----
            for (int j = 0; j < B; j++) {
                const float4 mb = sbatch_box[j];
                const uint2  mm = sbatch_meta[j];
                if (mb.x <= tx2hi && mb.z >= tx1lo) {
                    const float mar2 = (mb.z - mb.x) * (mb.w - mb.y);
#pragma unroll
                    for (int k = 0; k < PER; k++) {
                        if ((procm >> k) & 1u) continue;
                        if (t * PER + k == (int)mm.x) {
                            procm |= 1u << k;
                            if (orig[k] < out_size) out[orig[k]] = __uint_as_float(mm.y);
                            dirty = true;
                        } else {
                            const float iw = fmaxf(fminf(mb.z, x2[k]) - fmaxf(mb.x, x1[k]), 0.0f);
                            const float ih = fmaxf(fminf(mb.w, y2[k]) - fmaxf(mb.y, y1[k]), 0.0f);
                            const float inter = iw * ih;
                            if (inter > 0.0f) {
                                const float iou = __fdividef(inter, mar2 + area[k] - inter);
                                s[k] *= __expf(-2.0f * iou * iou);
                                dirty = true;
                            }
                        }
                    }
                }
            }
        } else {
            // ======= consumers: stream-apply members as they publish =======
            int applied = 0;
            while (true) {
                const int pub = ld_acq(&spub);
                while (applied < pub) {
                    const float4 mb = sbatch_box[applied];
                    const uint2  mm = sbatch_meta[applied];
                    if (t == 0 && (NBOX + step + applied) < out_size)
                        out[NBOX + step + applied] = (float)g_orig[mm.x];
                    if (mb.x <= tx2hi && mb.z >= tx1lo) {
                        const float mar2 = (mb.z - mb.x) * (mb.w - mb.y);
#pragma unroll
                        for (int k = 0; k < PER; k++) {
                            if ((procm >> k) & 1u) continue;
                            if (t * PER + k == (int)mm.x) {
                                procm |= 1u << k;
                                if (orig[k] < out_size) out[orig[k]] = __uint_as_float(mm.y);
                                dirty = true;
                            } else {
                                const float iw = fmaxf(fminf(mb.z, x2[k]) - fmaxf(mb.x, x1[k]), 0.0f);
                                const float ih = fmaxf(fminf(mb.w, y2[k]) - fmaxf(mb.y, y1[k]), 0.0f);
                                const float inter = iw * ih;
                                if (inter > 0.0f) {
                                    const float iou = __fdividef(inter, mar2 + area[k] - inter);
                                    s[k] *= __expf(-2.0f * iou * iou);
                                    dirty = true;
                                }
                            }
                        }
                    }
                    applied++;
                }
                const int dn = ld_acq(&sdone);
                if (dn >= 0 && applied >= (dn & 0xff)) break;
                __nanosleep(100);
            }
        }
        __syncthreads();   // bar2: batch fully applied everywhere

        const int dn = sdone;
        step += (dn & 0xff);
        if (dn & 0x100) { fro_final = 1; fpos_final = dn >> 9; break; }
    }

    // ---- frozen tail: all remaining steps re-select the same argmax ----
    if (fro_final && step < NBOX) {
        const int fo = g_orig[fpos_final];
        for (int j = step + t; j < NBOX; j += T) {
            if ((NBOX + j) < out_size) out[NBOX + j] = (float)fo;
        }
    }
}

extern "C" void kernel_launch(void* const* d_in, const int* in_sizes, int n_in,
                              void* d_out, int out_size)
{
    const float4* boxes;
    const float*  scores;
    if (in_sizes[0] == 4 * NBOX) {
        boxes  = (const float4*)d_in[0];
        scores = (const float*)d_in[1];
    } else {
        boxes  = (const float4*)d_in[1];
        scores = (const float*)d_in[0];
    }
    softnms_kernel<<<1, T>>>(boxes, scores, (float*)d_out, out_size);
}

// round 13
// speedup vs baseline: 1.0645x; 1.0645x over previous
#include <cuda_runtime.h>

#define NBOX 4096
#define T 1024
#define PER 4                  // NBOX / T
#define NWARP 32
#define PROD (NWARP - 1)       // producer = HIGHEST wid (hi-wid-first arbiter)
#define BMAX 64
#define THRESH 0.05f
#define FULL 0xffffffffu

__device__ float4 g_sbox[NBOX];
__device__ int    g_orig[NBOX];

__global__ __launch_bounds__(T, 1)
void softnms_kernel(const float4* __restrict__ boxes,
                    const float*  __restrict__ scores,
                    float* __restrict__ out, int out_size)
{
    __shared__ unsigned long long skv[NBOX];   // sort scratch
    __shared__ uint4    spoolA[NWARP];         // (k1, p1, k2, p2) exact keys
    __shared__ unsigned sm3[NWARP];            // per-warp 3rd-best value
    __shared__ float4   sbatch_box[BMAX];
    __shared__ uint2    sbatch_meta[BMAX];     // (sorted pos, exact score bits)
    __shared__ int      sB, sfro, sfpos;

    const int t    = threadIdx.x;
    const int lane = t & 31;
    const int wid  = t >> 5;

    // ---- init: zero score outputs, stage u64 sort keys ----
#pragma unroll
    for (int k = 0; k < PER; k++) {
        const int gi = t * PER + k;
        if (gi < out_size) out[gi] = 0.0f;
        skv[gi] = ((unsigned long long)__float_as_uint(boxes[gi].x) << 32)
                  | (unsigned)gi;
    }
    __syncthreads();

    // ---- bitonic sort ascending by x1 ----
    for (int k = 2; k <= NBOX; k <<= 1) {
        for (int j = k >> 1; j > 0; j >>= 1) {
#pragma unroll
            for (int e = t; e < NBOX; e += T) {
                const int ixj = e ^ j;
                if (ixj > e) {
                    const unsigned long long a = skv[e], c = skv[ixj];
                    const bool up = ((e & k) == 0);
                    if (up ? (a > c) : (a < c)) { skv[e] = c; skv[ixj] = a; }
                }
            }
            __syncthreads();
        }
    }

    // ---- load my PER sorted boxes; publish sorted tables ----
    float x1[PER], y1[PER], x2[PER], y2[PER], area[PER], s[PER];
    int   orig[PER];
    unsigned procm = 0;
    float tx2hi = 0.0f;
#pragma unroll
    for (int k = 0; k < PER; k++) {
        const int pos = t * PER + k;
        const int o   = (int)(unsigned)(skv[pos] & 0xffffffffu);
        orig[k] = o;
        const float4 b = boxes[o];
        x1[k] = b.x; y1[k] = b.y; x2[k] = b.z; y2[k] = b.w;
        area[k] = (b.z - b.x) * (b.w - b.y);
        s[k]    = scores[o];
        g_sbox[pos] = b;
        g_orig[pos] = o;
        tx2hi = fmaxf(tx2hi, b.z);
    }
    const float tx1lo = x1[0];
    __syncthreads();

    bool dirty = true;
    int  step  = 0;
    int  fro_final = 0, fpos_final = 0;

    while (step < NBOX) {
        // ========= rebuild per-warp top-2 (+3rd value), EXACT argmax =======
        if (__ballot_sync(FULL, dirty)) {
            unsigned b1 = 0, b2 = 0, b3 = 0, p1 = 0, p2 = 0;
#pragma unroll
            for (int k = 0; k < PER; k++) {
                if (!((procm >> k) & 1u)) {
                    const unsigned ub = __float_as_uint(s[k]);   // scores > 0
                    const unsigned up = (unsigned)(t * PER + k);
                    if (ub > b1)      { b3 = b2; b2 = b1; p2 = p1; b1 = ub; p1 = up; }
                    else if (ub > b2) { b3 = b2; b2 = ub; p2 = up; }
                    else if (ub > b3) { b3 = ub; }
                }
            }
            const unsigned m1   = __reduce_max_sync(FULL, b1);
            const unsigned bal1 = __ballot_sync(FULL, b1 == m1);
            const int s1        = __ffs(bal1) - 1;
            const unsigned q1   = __shfl_sync(FULL, p1, s1);
            const unsigned v2   = (lane == s1) ? b2 : b1;
            const unsigned vp2  = (lane == s1) ? p2 : p1;
            const unsigned m2   = __reduce_max_sync(FULL, v2);
            const unsigned bal2 = __ballot_sync(FULL, v2 == m2);
            const int s2        = __ffs(bal2) - 1;
            const unsigned q2   = __shfl_sync(FULL, vp2, s2);
            unsigned v3 = b1;
            if (lane == s1) v3 = b2;
            if (lane == s2) v3 = (s2 == s1) ? b3 : b2;
            const unsigned m3 = __reduce_max_sync(FULL, v3);
            if (lane == 0) { spoolA[wid] = make_uint4(m1, q1, m2, q2); sm3[wid] = m3; }
            dirty = false;
        }
        __syncthreads();   // bar1: pools visible; consumers park in bar2 next

        if (wid == PROD) {
            // ==== producer scans ALONE on a quiet SM (others sit in BAR) ===
            const uint4 a = spoolA[lane];
            unsigned k1 = a.x, pp1 = a.y, k2 = a.z, pp2 = a.w;
            const unsigned M3 = __reduce_max_sync(FULL, sm3[lane]);
            const float4 f1 = g_sbox[pp1]; const float a1 = (f1.z - f1.x) * (f1.w - f1.y);
            const float4 f2 = g_sbox[pp2]; const float a2 = (f2.z - f2.x) * (f2.w - f2.y);

            int B = 0, fz = 0; unsigned fp = 0;
            while (true) {
                const bool s1w      = (k1 >= k2);
                const unsigned kmax = s1w ? k1 : k2;
                const unsigned m    = __reduce_max_sync(FULL, kmax);
                if (m < M3) break;                   // pool no longer covers order
                const unsigned bal = __ballot_sync(FULL, kmax == m);
                const int src      = __ffs(bal) - 1;
                if (!(__uint_as_float(m) > THRESH)) {  // pool max == global max
                    fz = 1;
                    fp = __shfl_sync(FULL, s1w ? pp1 : pp2, src);
                    break;
                }
                const float mx1 = __shfl_sync(FULL, s1w ? f1.x : f2.x, src);
                const float my1 = __shfl_sync(FULL, s1w ? f1.y : f2.y, src);
                const float mx2 = __shfl_sync(FULL, s1w ? f1.z : f2.z, src);
                const float my2 = __shfl_sync(FULL, s1w ? f1.w : f2.w, src);
                const float mar = (mx2 - mx1) * (my2 - my1);
                const bool is_src = (lane == src);
                if (is_src) {                        // plain STS; bar2 publishes
                    sbatch_box[B]  = make_float4(mx1, my1, mx2, my2);
                    sbatch_meta[B] = make_uint2(s1w ? pp1 : pp2, m);
                }
                // consume winner slot (0 stays 0 through decays)
                k1 = (is_src &&  s1w) ? 0u : k1;
                k2 = (is_src && !s1w) ? 0u : k2;
                // unconditional bit-exact decay (inter==0 -> multiply by 1.0f)
                {
                    const float iw = fmaxf(fminf(mx2, f1.z) - fmaxf(mx1, f1.x), 0.0f);
                    const float ih = fmaxf(fminf(my2, f1.w) - fmaxf(my1, f1.y), 0.0f);
                    const float inter = iw * ih;
                    const float iou = __fdividef(inter, mar + a1 - inter);
                    k1 = __float_as_uint(__uint_as_float(k1) * __expf(-2.0f * iou * iou));
                }
                {
                    const float iw = fmaxf(fminf(mx2, f2.z) - fmaxf(mx1, f2.x), 0.0f);
                    const float ih = fmaxf(fminf(my2, f2.w) - fmaxf(my1, f2.y), 0.0f);
                    const float inter = iw * ih;
                    const float iou = __fdividef(inter, mar + a2 - inter);
                    k2 = __float_as_uint(__uint_as_float(k2) * __expf(-2.0f * iou * iou));
                }
                B++;
                if (B == BMAX) break;
            }
            __syncwarp();                            // all lanes' STS done
            if (lane == 0) { sB = B; sfro = fz; sfpos = (int)fp; }
        }
        __syncthreads();   // bar2: batch + flags visible to everyone

        const int B = sB;

        // ---- parallel idxs writes: thread j handles member j ----
        if (t < B && (NBOX + step + t) < out_size)
            out[NBOX + step + t] = (float)g_orig[sbatch_meta[t].x];

        // ---- apply batch decay: my PER boxes vs all B members ----
        for (int j = 0; j < B; j++) {
            const float4 mb = sbatch_box[j];       // LDS broadcast
            const uint2  mm = sbatch_meta[j];
            if (mb.x <= tx2hi && mb.z >= tx1lo) {  // x-interval skip (exact)
                const float mar = (mb.z - mb.x) * (mb.w - mb.y);
#pragma unroll
                for (int k = 0; k < PER; k++) {
                    if ((procm >> k) & 1u) continue;
                    if (t * PER + k == (int)mm.x) {
                        procm |= 1u << k;
                        if (orig[k] < out_size) out[orig[k]] = __uint_as_float(mm.y);
                        dirty = true;
                    } else {
                        const float iw = fmaxf(fminf(mb.z, x2[k]) - fmaxf(mb.x, x1[k]), 0.0f);
                        const float ih = fmaxf(fminf(mb.w, y2[k]) - fmaxf(mb.y, y1[k]), 0.0f);
                        const float inter = iw * ih;
                        if (inter > 0.0f) {
                            const float iou = __fdividef(inter, mar + area[k] - inter);
                            s[k] *= __expf(-2.0f * iou * iou);
                            dirty = true;
                        }
                    }
                }
            }
        }
        step += B;
        if (sfro) { fro_final = 1; fpos_final = sfpos; break; }
        // B == 0 without frozen cannot happen: first candidate is >= M3
    }

    // ---- frozen tail: all remaining steps re-select the same argmax ----
    if (fro_final && step < NBOX) {
        const int fo = g_orig[fpos_final];
        for (int j = step + t; j < NBOX; j += T) {
            if ((NBOX + j) < out_size) out[NBOX + j] = (float)fo;
        }
    }
}

extern "C" void kernel_launch(void* const* d_in, const int* in_sizes, int n_in,
                              void* d_out, int out_size)
{
    const float4* boxes;
    const float*  scores;
    if (in_sizes[0] == 4 * NBOX) {
        boxes  = (const float4*)d_in[0];
        scores = (const float*)d_in[1];
    } else {
        boxes  = (const float4*)d_in[1];
        scores = (const float*)d_in[0];
    }
    softnms_kernel<<<1, T>>>(boxes, scores, (float*)d_out, out_size);
}